// round 4
// baseline (speedup 1.0000x reference)
#include <cuda_runtime.h>

// FoldLayer gather, 2x2-output-tile per thread, persistent grid-stride,
// streaming cache hints (zero-reuse workload).
// Input:  patches (16, 64, 64, 9*128) f32 kernel-major; Output: (16,128,128,128) f32.

namespace {
constexpr int G   = 64;
constexpr int C4  = 32;                 // 128 channels / 4
constexpr int PATCH_F4 = 9 * C4;        // 288
constexpr int TOTAL = 16 * G * G * C4;  // 2,097,152 virtual threads
constexpr int BLK   = 128;
constexpr int GRID  = 148 * 11;         // 11 resident blocks/SM at 44 regs
}

__device__ __forceinline__ float4 ldcs4(const float4* p) {
    return __ldcs(p);
}

__global__ __launch_bounds__(BLK) void fold_tile_kernel(
    const float4* __restrict__ in, float4* __restrict__ out)
{
    const float4 z = make_float4(0.f, 0.f, 0.f, 0.f);
    for (unsigned idx = blockIdx.x * BLK + threadIdx.x; idx < TOTAL;
         idx += GRID * BLK)
    {
        unsigned c4 = idx & (C4 - 1);
        unsigned t  = idx >> 5;
        unsigned tx = t & (G - 1);  t >>= 6;
        unsigned ty = t & (G - 1);
        unsigned b  = t >> 6;

        const bool vx = (tx + 1) < G;
        const bool vy = (ty + 1) < G;

        const float4* p = in + c4;
        unsigned cell00 = ((b * G + ty) * G + tx) * PATCH_F4;
        unsigned cell01 = cell00 + PATCH_F4;          // (ty, tx+1)
        unsigned cell10 = cell00 + G * PATCH_F4;      // (ty+1, tx)
        unsigned cell11 = cell10 + PATCH_F4;          // (ty+1, tx+1)

        // cell(ty,tx): (i,j) in {1,2}x{1,2}
        float4 a11 = ldcs4(p + cell00 + 4 * C4);   // (1,1)
        float4 a12 = ldcs4(p + cell00 + 5 * C4);   // (1,2)
        float4 a21 = ldcs4(p + cell00 + 7 * C4);   // (2,1)
        float4 a22 = ldcs4(p + cell00 + 8 * C4);   // (2,2)
        // cell(ty,tx+1): j=0, i in {1,2}
        float4 b10 = vx ? ldcs4(p + cell01 + 3 * C4) : z;   // (1,0)
        float4 b20 = vx ? ldcs4(p + cell01 + 6 * C4) : z;   // (2,0)
        // cell(ty+1,tx): i=0, j in {1,2}
        float4 c01 = vy ? ldcs4(p + cell10 + 1 * C4) : z;   // (0,1)
        float4 c02 = vy ? ldcs4(p + cell10 + 2 * C4) : z;   // (0,2)
        // cell(ty+1,tx+1): (0,0)
        float4 d00 = (vx && vy) ? ldcs4(p + cell11) : z;

        float4 acc01, acc10, acc11;
        acc01.x = a12.x + b10.x; acc01.y = a12.y + b10.y;
        acc01.z = a12.z + b10.z; acc01.w = a12.w + b10.w;
        acc10.x = a21.x + c01.x; acc10.y = a21.y + c01.y;
        acc10.z = a21.z + c01.z; acc10.w = a21.w + c01.w;
        acc11.x = (a22.x + b20.x) + (c02.x + d00.x);
        acc11.y = (a22.y + b20.y) + (c02.y + d00.y);
        acc11.z = (a22.z + b20.z) + (c02.z + d00.z);
        acc11.w = (a22.w + b20.w) + (c02.w + d00.w);

        // out index: ((b*128 + yo)*128 + xo)*32 + c4, yo=2ty, xo=2tx
        unsigned o00 = (((b << 7) + (ty << 1)) << 7) + (tx << 1);
        o00 = (o00 << 5) + c4;
        __stcs(&out[o00],            a11);     // (yo, xo)
        __stcs(&out[o00 + C4],       acc01);   // (yo, xo+1)
        __stcs(&out[o00 + 128 * C4], acc10);   // (yo+1, xo)
        __stcs(&out[o00 + 129 * C4], acc11);   // (yo+1, xo+1)
    }
}

extern "C" void kernel_launch(void* const* d_in, const int* in_sizes, int n_in,
                              void* d_out, int out_size) {
    (void)in_sizes; (void)n_in; (void)out_size;
    const float4* in = (const float4*)d_in[0];
    float4* out = (float4*)d_out;
    fold_tile_kernel<<<GRID, BLK>>>(in, out);
}

// round 5
// speedup vs baseline: 1.0465x; 1.0465x over previous
#include <cuda_runtime.h>

// FoldLayer gather, 2x2-output-tile per thread (R2 shape), with forced
// 6 blocks/SM via launch bounds to deepen in-flight load queue.
// Input:  patches (16, 64, 64, 9*128) f32 kernel-major; Output: (16,128,128,128) f32.

namespace {
constexpr int G   = 64;
constexpr int C4  = 32;                 // 128 channels / 4
constexpr int PATCH_F4 = 9 * C4;        // 288
}

__global__ __launch_bounds__(256, 6) void fold_tile_kernel(
    const float4* __restrict__ in, float4* __restrict__ out)
{
    int idx = blockIdx.x * blockDim.x + threadIdx.x;
    int c4 = idx & (C4 - 1);
    int t  = idx >> 5;
    int tx = t & (G - 1);  t >>= 6;
    int ty = t & (G - 1);
    int b  = t >> 6;

    const bool vx = (tx + 1) < G;
    const bool vy = (ty + 1) < G;

    const float4* p = in + c4;
    int cell00 = ((b * G + ty) * G + tx) * PATCH_F4;
    int cell01 = cell00 + PATCH_F4;          // (ty, tx+1)
    int cell10 = cell00 + G * PATCH_F4;      // (ty+1, tx)
    int cell11 = cell10 + PATCH_F4;          // (ty+1, tx+1)

    // out index: ((b*128 + yo)*128 + xo)*32 + c4, yo=2ty, xo=2tx
    int o00 = (((b << 7) + (ty << 1)) << 7) + (tx << 1);
    o00 = (o00 << 5) + c4;

    const float4 z = make_float4(0.f, 0.f, 0.f, 0.f);
    // cell(ty,tx): (i,j) in {1,2}x{1,2}
    float4 a11 = __ldg(p + cell00 + 4 * C4);   // (1,1)
    float4 a12 = __ldg(p + cell00 + 5 * C4);   // (1,2)
    float4 a21 = __ldg(p + cell00 + 7 * C4);   // (2,1)
    float4 a22 = __ldg(p + cell00 + 8 * C4);   // (2,2)
    // cell(ty,tx+1): j=0, i in {1,2}
    float4 b10 = vx ? __ldg(p + cell01 + 3 * C4) : z;   // (1,0)
    float4 b20 = vx ? __ldg(p + cell01 + 6 * C4) : z;   // (2,0)
    // cell(ty+1,tx): i=0, j in {1,2}
    float4 c01 = vy ? __ldg(p + cell10 + 1 * C4) : z;   // (0,1)
    float4 c02 = vy ? __ldg(p + cell10 + 2 * C4) : z;   // (0,2)
    // cell(ty+1,tx+1): (0,0)
    float4 d00 = (vx && vy) ? __ldg(p + cell11) : z;

    out[o00] = a11;                           // (yo, xo) — pure copy, retire early

    float4 acc01, acc10, acc11;
    acc01.x = a12.x + b10.x; acc01.y = a12.y + b10.y;
    acc01.z = a12.z + b10.z; acc01.w = a12.w + b10.w;
    out[o00 + C4] = acc01;                    // (yo, xo+1)

    acc10.x = a21.x + c01.x; acc10.y = a21.y + c01.y;
    acc10.z = a21.z + c01.z; acc10.w = a21.w + c01.w;
    out[o00 + 128 * C4] = acc10;              // (yo+1, xo)

    acc11.x = (a22.x + b20.x) + (c02.x + d00.x);
    acc11.y = (a22.y + b20.y) + (c02.y + d00.y);
    acc11.z = (a22.z + b20.z) + (c02.z + d00.z);
    acc11.w = (a22.w + b20.w) + (c02.w + d00.w);
    out[o00 + 129 * C4] = acc11;              // (yo+1, xo+1)
}

extern "C" void kernel_launch(void* const* d_in, const int* in_sizes, int n_in,
                              void* d_out, int out_size) {
    (void)in_sizes; (void)n_in; (void)out_size;
    const float4* in = (const float4*)d_in[0];
    float4* out = (float4*)d_out;
    const int total = 16 * G * G * C4;   // 2,097,152 threads
    fold_tile_kernel<<<total / 256, 256>>>(in, out);
}